// round 16
// baseline (speedup 1.0000x reference)
#include <cuda_runtime.h>

typedef unsigned long long u64;

#define Bn 8
#define Cn 64
#define Hn 128
#define Wn 128
#define PLANE (Hn * Wn)
#define NQ 26
#define NROWS (Bn * Hn)

// L2-resident scratch (device globals: allocation-free per harness rules)
__device__ u64 g_part[4][NROWS][NQ][32];     // 27.3 MB partial sums
__device__ u64 g_wbuf[NROWS][9][2][32];      // 4.7 MB packed weights

__device__ __forceinline__ u64 pk(float a, float b) {
    u64 r; asm("mov.b64 %0, {%1, %2};" : "=l"(r) : "f"(a), "f"(b)); return r;
}
__device__ __forceinline__ void unpk(u64 v, float& a, float& b) {
    asm("mov.b64 {%0, %1}, %2;" : "=f"(a), "=f"(b) : "l"(v));
}
__device__ __forceinline__ u64 fma2(u64 a, u64 b, u64 c) {
    u64 d; asm("fma.rn.f32x2 %0, %1, %2, %3;" : "=l"(d) : "l"(a), "l"(b), "l"(c)); return d;
}
__device__ __forceinline__ u64 add2(u64 a, u64 b) {
    u64 d; asm("add.rn.f32x2 %0, %1, %2;" : "=l"(d) : "l"(a), "l"(b)); return d;
}

// ---------------- kA: per-16-channel partial sums (X, S, F) ----------------
__global__ void __launch_bounds__(64)
kA(const float* __restrict__ fe, const float* __restrict__ fu) {
    const int tid = threadIdx.x;
    const int w = tid >> 5, l = tid & 31;
    const int cg = blockIdx.x;            // 0..1
    const int rid = blockIdx.y;           // b*128 + r
    const int b = rid >> 7, r = rid & 127;
    const int g = cg * 2 + w;             // 4 channel groups of 16
    const int c0 = g * 16;
    const int x0 = l * 4;
    const bool pm = (r > 0), pp = (r < Hn - 1);

    const size_t base = ((size_t)b * Cn + c0) * PLANE + (size_t)r * Wn + x0;
    const float* fup = fu + base;
    const float* fep = fe + base;

    u64 X2[9][2], S2[3][2], F2[2];
    #pragma unroll
    for (int k = 0; k < 9; ++k) { X2[k][0] = 0ull; X2[k][1] = 0ull; }
    #pragma unroll
    for (int d = 0; d < 3; ++d) { S2[d][0] = 0ull; S2[d][1] = 0ull; }
    F2[0] = 0ull; F2[1] = 0ull;

    const float4 z4 = make_float4(0.f, 0.f, 0.f, 0.f);

    #pragma unroll 4
    for (int c = 0; c < 16; ++c) {
        const float* uc = fup + c * PLANE;
        float4 vr[3];
        vr[0] = pm ? __ldg((const float4*)(uc - Wn)) : z4;
        vr[1] = __ldg((const float4*)uc);
        vr[2] = pp ? __ldg((const float4*)(uc + Wn)) : z4;
        float4 f4 = __ldg((const float4*)(fep + c * PLANE));

        u64 fe01 = pk(f4.x, f4.y), fe23 = pk(f4.z, f4.w);
        F2[0] = fma2(fe01, fe01, F2[0]);
        F2[1] = fma2(fe23, fe23, F2[1]);

        #pragma unroll
        for (int dr = 0; dr < 3; ++dr) {
            float4 v = vr[dr];
            float L = __shfl_up_sync(0xffffffffu, v.w, 1);   if (l == 0)  L = 0.f;
            float R = __shfl_down_sync(0xffffffffu, v.x, 1); if (l == 31) R = 0.f;
            u64 c01 = pk(v.x, v.y), c23 = pk(v.z, v.w);
            u64 l01 = pk(L, v.x),   yz  = pk(v.y, v.z), r23 = pk(v.w, R);

            S2[dr][0] = fma2(c01, c01, S2[dr][0]);
            S2[dr][1] = fma2(c23, c23, S2[dr][1]);

            X2[dr*3+0][0] = fma2(l01, fe01, X2[dr*3+0][0]);
            X2[dr*3+0][1] = fma2(yz,  fe23, X2[dr*3+0][1]);
            X2[dr*3+1][0] = fma2(c01, fe01, X2[dr*3+1][0]);
            X2[dr*3+1][1] = fma2(c23, fe23, X2[dr*3+1][1]);
            X2[dr*3+2][0] = fma2(yz,  fe01, X2[dr*3+2][0]);
            X2[dr*3+2][1] = fma2(r23, fe23, X2[dr*3+2][1]);
        }
    }

    // Coalesced partial write: stride 32 u64 between q-slots
    u64* dst = &g_part[g][rid][0][l];
    #pragma unroll
    for (int k = 0; k < 9; ++k) {
        dst[(2*k)   * 32] = X2[k][0];
        dst[(2*k+1) * 32] = X2[k][1];
    }
    #pragma unroll
    for (int d = 0; d < 3; ++d) {
        dst[(18+2*d) * 32] = S2[d][0];
        dst[(19+2*d) * 32] = S2[d][1];
    }
    dst[24 * 32] = F2[0];
    dst[25 * 32] = F2[1];
}

// ---------------- kB: combine partials, softmax -> weights ----------------
__global__ void __launch_bounds__(64) kB() {
    const int tid = threadIdx.x;
    const int w = tid >> 5, l = tid & 31;
    const int rid = blockIdx.x * 2 + w;      // 512 blocks x 2 warps = 1024 rows

    u64 X2[9][2], S2[3][2], F2[2];
    {
        const u64* p0 = &g_part[0][rid][0][l];
        const u64* p1 = &g_part[1][rid][0][l];
        const u64* p2 = &g_part[2][rid][0][l];
        const u64* p3 = &g_part[3][rid][0][l];
        #pragma unroll
        for (int k = 0; k < 9; ++k) {
            X2[k][0] = add2(add2(p0[(2*k)*32],   p1[(2*k)*32]),
                            add2(p2[(2*k)*32],   p3[(2*k)*32]));
            X2[k][1] = add2(add2(p0[(2*k+1)*32], p1[(2*k+1)*32]),
                            add2(p2[(2*k+1)*32], p3[(2*k+1)*32]));
        }
        #pragma unroll
        for (int d = 0; d < 3; ++d) {
            S2[d][0] = add2(add2(p0[(18+2*d)*32], p1[(18+2*d)*32]),
                            add2(p2[(18+2*d)*32], p3[(18+2*d)*32]));
            S2[d][1] = add2(add2(p0[(19+2*d)*32], p1[(19+2*d)*32]),
                            add2(p2[(19+2*d)*32], p3[(19+2*d)*32]));
        }
        F2[0] = add2(add2(p0[24*32], p1[24*32]), add2(p2[24*32], p3[24*32]));
        F2[1] = add2(add2(p0[25*32], p1[25*32]), add2(p2[25*32], p3[25*32]));
    }

    float Xs[9][4], Ss[3][6], Fs[4];   // Ss[dr] = {L, s0, s1, s2, s3, R}
    #pragma unroll
    for (int k = 0; k < 9; ++k) {
        unpk(X2[k][0], Xs[k][0], Xs[k][1]);
        unpk(X2[k][1], Xs[k][2], Xs[k][3]);
    }
    #pragma unroll
    for (int d = 0; d < 3; ++d) {
        unpk(S2[d][0], Ss[d][1], Ss[d][2]);
        unpk(S2[d][1], Ss[d][3], Ss[d][4]);
        float SL = __shfl_up_sync(0xffffffffu, Ss[d][4], 1);   if (l == 0)  SL = 0.f;
        float SR = __shfl_down_sync(0xffffffffu, Ss[d][1], 1); if (l == 31) SR = 0.f;
        Ss[d][0] = SL; Ss[d][5] = SR;
    }
    unpk(F2[0], Fs[0], Fs[1]);
    unpk(F2[1], Fs[2], Fs[3]);

    float wtmp[9][4];
    #pragma unroll
    for (int p = 0; p < 4; ++p) {
        float F = Fs[p];
        float s = 0.f;
        #pragma unroll
        for (int dr = 0; dr < 3; ++dr) {
            #pragma unroll
            for (int dc = 0; dc < 3; ++dc) {
                float Sv = Ss[dr][p + dc];
                float d2 = fmaf(-2.f, Xs[dr*3+dc][p], Sv + F);
                float dd = sqrtf(fmaxf(d2, 0.f));
                float e = __expf(-dd);
                wtmp[dr*3+dc][p] = e;
                s += e;
            }
        }
        float inv = 1.f / s;
        #pragma unroll
        for (int k = 0; k < 9; ++k) wtmp[k][p] *= inv;
    }
    #pragma unroll
    for (int k = 0; k < 9; ++k) {
        g_wbuf[rid][k][0][l] = pk(wtmp[k][0], wtmp[k][1]);
        g_wbuf[rid][k][1][l] = pk(wtmp[k][2], wtmp[k][3]);
    }
}

// ---------------- kC: weighted neighbor sum + fe -> out ----------------
__global__ void __launch_bounds__(64)
kC(const float* __restrict__ fe, const float* __restrict__ fu,
   float* __restrict__ out) {
    const int tid = threadIdx.x;
    const int w = tid >> 5, l = tid & 31;
    const int cg = blockIdx.x;
    const int rid = blockIdx.y;
    const int b = rid >> 7, r = rid & 127;
    const int g = cg * 2 + w;
    const int c0 = g * 16;
    const int x0 = l * 4;
    const bool pm = (r > 0), pp = (r < Hn - 1);

    u64 w2[9][2];
    #pragma unroll
    for (int k = 0; k < 9; ++k) {
        w2[k][0] = g_wbuf[rid][k][0][l];
        w2[k][1] = g_wbuf[rid][k][1][l];
    }

    const size_t base = ((size_t)b * Cn + c0) * PLANE + (size_t)r * Wn + x0;
    const float* fup = fu + base;
    const float* fep = fe + base;
    float* op = out + base;
    const float4 z4 = make_float4(0.f, 0.f, 0.f, 0.f);

    #pragma unroll 4
    for (int c = 0; c < 16; ++c) {
        const float* uc = fup + c * PLANE;
        float4 vr[3];
        vr[0] = pm ? __ldg((const float4*)(uc - Wn)) : z4;
        vr[1] = __ldg((const float4*)uc);
        vr[2] = pp ? __ldg((const float4*)(uc + Wn)) : z4;
        float4 f4 = __ldg((const float4*)(fep + c * PLANE));

        u64 acc0 = pk(f4.x, f4.y);
        u64 acc1 = pk(f4.z, f4.w);
        #pragma unroll
        for (int dr = 0; dr < 3; ++dr) {
            float4 v = vr[dr];
            float L = __shfl_up_sync(0xffffffffu, v.w, 1);   if (l == 0)  L = 0.f;
            float R = __shfl_down_sync(0xffffffffu, v.x, 1); if (l == 31) R = 0.f;
            u64 c01 = pk(v.x, v.y), c23 = pk(v.z, v.w);
            u64 l01 = pk(L, v.x),   yz  = pk(v.y, v.z), r23 = pk(v.w, R);

            acc0 = fma2(l01, w2[dr*3+0][0], acc0);
            acc1 = fma2(yz,  w2[dr*3+0][1], acc1);
            acc0 = fma2(c01, w2[dr*3+1][0], acc0);
            acc1 = fma2(c23, w2[dr*3+1][1], acc1);
            acc0 = fma2(yz,  w2[dr*3+2][0], acc0);
            acc1 = fma2(r23, w2[dr*3+2][1], acc1);
        }
        float4 o4;
        unpk(acc0, o4.x, o4.y);
        unpk(acc1, o4.z, o4.w);
        *(float4*)(op + c * PLANE) = o4;
    }
}

extern "C" void kernel_launch(void* const* d_in, const int* in_sizes, int n_in,
                              void* d_out, int out_size) {
    const float* fe = (const float*)d_in[0];   // fe_lv
    const float* fu = (const float*)d_in[1];   // fused_features
    float* out = (float*)d_out;

    dim3 grdA(2, NROWS);
    kA<<<grdA, 64>>>(fe, fu);
    kB<<<NROWS / 2, 64>>>();
    kC<<<grdA, 64>>>(fe, fu, out);
}

// round 17
// speedup vs baseline: 2.2186x; 2.2186x over previous
#include <cuda_runtime.h>

typedef unsigned long long u64;

#define Bn 8
#define Cn 64
#define Hn 128
#define Wn 128
#define PLANE (Hn * Wn)
#define NPAD 27

__device__ __forceinline__ u64 pk(float a, float b) {
    u64 r; asm("mov.b64 %0, {%1, %2};" : "=l"(r) : "f"(a), "f"(b)); return r;
}
__device__ __forceinline__ void unpk(u64 v, float& a, float& b) {
    asm("mov.b64 {%0, %1}, %2;" : "=f"(a), "=f"(b) : "l"(v));
}
__device__ __forceinline__ u64 fma2(u64 a, u64 b, u64 c) {
    u64 d; asm("fma.rn.f32x2 %0, %1, %2, %3;" : "=l"(d) : "l"(a), "l"(b), "l"(c)); return d;
}
__device__ __forceinline__ u64 add2(u64 a, u64 b) {
    u64 d; asm("add.rn.f32x2 %0, %1, %2;" : "=l"(d) : "l"(a), "l"(b)); return d;
}

// Weighted 3x3 row-sum for one channel: vr[3] fused rows, f4 fe, w2 packed weights.
__device__ __forceinline__ float4 p3_body(const float4 vr[3], float4 f4,
                                          const u64 w2[9][2], int l) {
    u64 acc0 = pk(f4.x, f4.y);
    u64 acc1 = pk(f4.z, f4.w);
    #pragma unroll
    for (int dr = 0; dr < 3; ++dr) {
        float4 v = vr[dr];
        float L = __shfl_up_sync(0xffffffffu, v.w, 1);   if (l == 0)  L = 0.f;
        float R = __shfl_down_sync(0xffffffffu, v.x, 1); if (l == 31) R = 0.f;
        u64 c01 = pk(v.x, v.y), c23 = pk(v.z, v.w);
        u64 l01 = pk(L, v.x),   yz  = pk(v.y, v.z), r23 = pk(v.w, R);

        acc0 = fma2(l01, w2[dr*3+0][0], acc0);
        acc1 = fma2(yz,  w2[dr*3+0][1], acc1);
        acc0 = fma2(c01, w2[dr*3+1][0], acc0);
        acc1 = fma2(c23, w2[dr*3+1][1], acc1);
        acc0 = fma2(yz,  w2[dr*3+2][0], acc0);
        acc1 = fma2(r23, w2[dr*3+2][1], acc1);
    }
    float4 o4;
    unpk(acc0, o4.x, o4.y);
    unpk(acc1, o4.z, o4.w);
    return o4;
}

__global__ void __launch_bounds__(64)
fused_kernel(const float* __restrict__ fe, const float* __restrict__ fu,
             float* __restrict__ out) {
    __shared__ u64 red[2][32][NPAD];

    const int tid = threadIdx.x;
    const int w = tid >> 5, l = tid & 31;     // 2 warps: channel groups of 32
    const int b = blockIdx.x >> 7;            // 1024 blocks = 8 batches x 128 rows
    const int r = blockIdx.x & 127;
    const int x0 = l * 4;
    const int c0 = w * 32;
    const bool pm = (r > 0), pp = (r < Hn - 1);

    const size_t base = ((size_t)b * Cn + c0) * PLANE + (size_t)r * Wn + x0;
    const float* fup = fu + base;
    const float* fep = fe + base;

    // ---------------- Phase 1: accumulate X (9 cross terms), S (3 rows), F ----------------
    u64 X2[9][2], S2[3][2], F2[2];
    #pragma unroll
    for (int k = 0; k < 9; ++k) { X2[k][0] = 0ull; X2[k][1] = 0ull; }
    #pragma unroll
    for (int d = 0; d < 3; ++d) { S2[d][0] = 0ull; S2[d][1] = 0ull; }
    F2[0] = 0ull; F2[1] = 0ull;

    const float4 z4 = make_float4(0.f, 0.f, 0.f, 0.f);

    #pragma unroll 4
    for (int c = 0; c < 32; ++c) {
        const float* uc = fup + c * PLANE;
        float4 vr[3];
        vr[0] = pm ? __ldg((const float4*)(uc - Wn)) : z4;
        vr[1] = __ldg((const float4*)uc);
        vr[2] = pp ? __ldg((const float4*)(uc + Wn)) : z4;
        float4 f4 = __ldg((const float4*)(fep + c * PLANE));

        u64 fe01 = pk(f4.x, f4.y), fe23 = pk(f4.z, f4.w);
        F2[0] = fma2(fe01, fe01, F2[0]);
        F2[1] = fma2(fe23, fe23, F2[1]);

        #pragma unroll
        for (int dr = 0; dr < 3; ++dr) {
            float4 v = vr[dr];
            float L = __shfl_up_sync(0xffffffffu, v.w, 1);   if (l == 0)  L = 0.f;
            float R = __shfl_down_sync(0xffffffffu, v.x, 1); if (l == 31) R = 0.f;
            u64 c01 = pk(v.x, v.y), c23 = pk(v.z, v.w);
            u64 l01 = pk(L, v.x),   yz  = pk(v.y, v.z), r23 = pk(v.w, R);

            S2[dr][0] = fma2(c01, c01, S2[dr][0]);
            S2[dr][1] = fma2(c23, c23, S2[dr][1]);

            X2[dr*3+0][0] = fma2(l01, fe01, X2[dr*3+0][0]);
            X2[dr*3+0][1] = fma2(yz,  fe23, X2[dr*3+0][1]);
            X2[dr*3+1][0] = fma2(c01, fe01, X2[dr*3+1][0]);
            X2[dr*3+1][1] = fma2(c23, fe23, X2[dr*3+1][1]);
            X2[dr*3+2][0] = fma2(yz,  fe01, X2[dr*3+2][0]);
            X2[dr*3+2][1] = fma2(r23, fe23, X2[dr*3+2][1]);
        }
    }

    // ---- Prefetch first 2 channels of phase 3 (completes under reduction+softmax) ----
    float4 p_vr[2][3], p_f4[2];
    #pragma unroll
    for (int pc = 0; pc < 2; ++pc) {
        const float* uc = fup + pc * PLANE;
        p_vr[pc][0] = pm ? __ldg((const float4*)(uc - Wn)) : z4;
        p_vr[pc][1] = __ldg((const float4*)uc);
        p_vr[pc][2] = pp ? __ldg((const float4*)(uc + Wn)) : z4;
        p_f4[pc] = __ldg((const float4*)(fep + pc * PLANE));
    }

    // ---------------- Cross-warp reduction (sum the 2 channel groups) ----------------
    {
        u64* slot = red[w][l];
        #pragma unroll
        for (int k = 0; k < 9; ++k) { slot[2*k] = X2[k][0]; slot[2*k+1] = X2[k][1]; }
        #pragma unroll
        for (int d = 0; d < 3; ++d) { slot[18+2*d] = S2[d][0]; slot[19+2*d] = S2[d][1]; }
        slot[24] = F2[0]; slot[25] = F2[1];
    }
    __syncthreads();
    {
        #pragma unroll
        for (int k = 0; k < 9; ++k) {
            X2[k][0] = add2(red[0][l][2*k],   red[1][l][2*k]);
            X2[k][1] = add2(red[0][l][2*k+1], red[1][l][2*k+1]);
        }
        #pragma unroll
        for (int d = 0; d < 3; ++d) {
            S2[d][0] = add2(red[0][l][18+2*d], red[1][l][18+2*d]);
            S2[d][1] = add2(red[0][l][19+2*d], red[1][l][19+2*d]);
        }
        F2[0] = add2(red[0][l][24], red[1][l][24]);
        F2[1] = add2(red[0][l][25], red[1][l][25]);
    }

    // ---------------- Phase 2: distances + softmax -> packed weights ----------------
    float Xs[9][4], Ss[3][6], Fs[4];   // Ss[dr] = {L, s0, s1, s2, s3, R}
    #pragma unroll
    for (int k = 0; k < 9; ++k) {
        unpk(X2[k][0], Xs[k][0], Xs[k][1]);
        unpk(X2[k][1], Xs[k][2], Xs[k][3]);
    }
    #pragma unroll
    for (int d = 0; d < 3; ++d) {
        unpk(S2[d][0], Ss[d][1], Ss[d][2]);
        unpk(S2[d][1], Ss[d][3], Ss[d][4]);
        float SL = __shfl_up_sync(0xffffffffu, Ss[d][4], 1);   if (l == 0)  SL = 0.f;
        float SR = __shfl_down_sync(0xffffffffu, Ss[d][1], 1); if (l == 31) SR = 0.f;
        Ss[d][0] = SL; Ss[d][5] = SR;
    }
    unpk(F2[0], Fs[0], Fs[1]);
    unpk(F2[1], Fs[2], Fs[3]);

    u64 w2[9][2];
    float wtmp[9][4];
    #pragma unroll
    for (int p = 0; p < 4; ++p) {
        float F = Fs[p];
        float s = 0.f;
        #pragma unroll
        for (int dr = 0; dr < 3; ++dr) {
            #pragma unroll
            for (int dc = 0; dc < 3; ++dc) {
                float Sv = Ss[dr][p + dc];           // p+dc in [0,5]
                float d2 = fmaf(-2.f, Xs[dr*3+dc][p], Sv + F);
                float dd = sqrtf(fmaxf(d2, 0.f));
                float e = __expf(-dd);               // dist >= 0: no overflow, skip max-shift
                wtmp[dr*3+dc][p] = e;
                s += e;
            }
        }
        float inv = 1.f / s;
        #pragma unroll
        for (int k = 0; k < 9; ++k) wtmp[k][p] *= inv;
    }
    #pragma unroll
    for (int k = 0; k < 9; ++k) {
        w2[k][0] = pk(wtmp[k][0], wtmp[k][1]);
        w2[k][1] = pk(wtmp[k][2], wtmp[k][3]);
    }

    // ---------------- Phase 3: weighted neighbor sum + fe -> out ----------------
    float* op = out + base;

    // Peeled channels 0..1 from prefetched registers
    #pragma unroll
    for (int pc = 0; pc < 2; ++pc) {
        float4 o4 = p3_body(p_vr[pc], p_f4[pc], w2, l);
        __stcs((float4*)(op + pc * PLANE), o4);    // streaming store: don't evict fu/fe
    }

    #pragma unroll 4
    for (int c = 2; c < 32; ++c) {
        const float* uc = fup + c * PLANE;
        float4 vr[3];
        vr[0] = pm ? __ldg((const float4*)(uc - Wn)) : z4;
        vr[1] = __ldg((const float4*)uc);
        vr[2] = pp ? __ldg((const float4*)(uc + Wn)) : z4;
        float4 f4 = __ldg((const float4*)(fep + c * PLANE));

        float4 o4 = p3_body(vr, f4, w2, l);
        __stcs((float4*)(op + c * PLANE), o4);     // streaming store
    }
}

extern "C" void kernel_launch(void* const* d_in, const int* in_sizes, int n_in,
                              void* d_out, int out_size) {
    const float* fe = (const float*)d_in[0];   // fe_lv
    const float* fu = (const float*)d_in[1];   // fused_features
    float* out = (float*)d_out;

    fused_kernel<<<Bn * Hn, 64>>>(fe, fu, out);   // 1024 blocks x 64 threads
}